// round 1
// baseline (speedup 1.0000x reference)
#include <cuda_runtime.h>
#include <cstdint>

#define FULLMASK 0xFFFFFFFFu

// ---- problem constants ----
#define DIMN   5
#define NSAVE  64
#define BATCH  4096
#define EPSV   1e-6f
#define DT0V   0.1f

// Tsit5 tableau (fp32)
#define A21f 0.161f
#define A31f -0.008480655492356989f
#define A32f 0.335480655492357f
#define A41f 2.8971530571054935f
#define A42f -6.359448489975075f
#define A43f 4.3622954328695815f
#define A51f 5.325864828439257f
#define A52f -11.748883564062828f
#define A53f 7.4955393428898365f
#define A54f -0.09249506636175525f
#define A61f 5.86145544294642f
#define A62f -12.92096931784711f
#define A63f 8.159367898576159f
#define A64f -0.071584973281401f
#define A65f -0.028269050394068383f
#define B1f 0.09646076681806523f
#define B2f 0.01f
#define B3f 0.4798896504144996f
#define B4f 1.379008574103742f
#define B5f -3.290069515436081f
#define B6f 2.324710524099774f
#define E1f -0.00178001105222577714f
#define E2f -0.0008164344596567469f
#define E3f 0.007880878010261995f
#define E4f -0.1447110071732629f
#define E5f 0.5823571654525552f
#define E6f -0.45808210592918697f
#define E7f 0.015151515151515152f

// softplus = logaddexp(x, 0) = max(x,0) + log1p(exp(-|x|))  (matches jax.nn.softplus)
static __device__ __forceinline__ float sp(float x) {
    return fmaxf(x, 0.0f) + log1pf(expf(-fabsf(x)));
}

static __device__ __forceinline__ void fma2(unsigned long long &d,
                                            unsigned long long a,
                                            unsigned long long b) {
    asm("fma.rn.f32x2 %0, %1, %2, %0;" : "+l"(d) : "l"(a), "l"(b));
}
static __device__ __forceinline__ float2 asf2(unsigned long long u) {
    float2 f;
    asm("mov.b64 {%0, %1}, %2;" : "=f"(f.x), "=f"(f.y) : "l"(u));
    return f;
}

// 64->64 layer for this warp: lane j computes output neurons j and j+32.
// Wrow: smem, row-major, row stride 68 floats (conflict-free LDS.128).
// hbuf: 64 floats of input activations (per-warp smem scratch, 16B aligned).
static __device__ __forceinline__ float2 layer64(const float* __restrict__ Wrow,
                                                 const float* __restrict__ bsm,
                                                 const float* __restrict__ hbuf,
                                                 int j) {
    const ulonglong2* hp = reinterpret_cast<const ulonglong2*>(hbuf);
    const ulonglong2* w0 = reinterpret_cast<const ulonglong2*>(Wrow + j * 68);
    const ulonglong2* w1 = reinterpret_cast<const ulonglong2*>(Wrow + (j + 32) * 68);
    unsigned long long a0 = 0ull, a1 = 0ull, a2 = 0ull, a3 = 0ull;
#pragma unroll
    for (int half = 0; half < 2; ++half) {
        ulonglong2 h[8];
#pragma unroll
        for (int c = 0; c < 8; ++c) h[c] = hp[half * 8 + c];
#pragma unroll
        for (int c = 0; c < 8; ++c) {
            ulonglong2 w = w0[half * 8 + c];
            fma2(a0, w.x, h[c].x);
            fma2(a1, w.y, h[c].y);
        }
#pragma unroll
        for (int c = 0; c < 8; ++c) {
            ulonglong2 w = w1[half * 8 + c];
            fma2(a2, w.x, h[c].x);
            fma2(a3, w.y, h[c].y);
        }
    }
    float2 f0 = asf2(a0), f1 = asf2(a1), f2 = asf2(a2), f3 = asf2(a3);
    float2 r;
    r.x = bsm[j]      + ((f0.x + f0.y) + (f1.x + f1.y));
    r.y = bsm[j + 32] + ((f2.x + f2.y) + (f3.x + f3.y));
    return r;
}

// Full MLP vector field evaluation. ya[5] replicated across lanes -> k[5] replicated.
static __device__ __forceinline__ void feval(const float ya[DIMN], float k[DIMN],
                                             const float* sW1, const float* sb1,
                                             const float* sW2, const float* sb2,
                                             const float* sW3, const float* sb3,
                                             const float2* sW4, const float* sb4,
                                             float* buf0, float* buf1, int j) {
    // layer 1: 5 -> 64
    float a0 = sb1[j], a1 = sb1[j + 32];
#pragma unroll
    for (int i = 0; i < DIMN; ++i) {
        a0 = fmaf(sW1[j * 5 + i], ya[i], a0);
        a1 = fmaf(sW1[(j + 32) * 5 + i], ya[i], a1);
    }
    float h0 = sp(a0), h1 = sp(a1);
    buf0[j] = h0; buf0[j + 32] = h1;
    __syncwarp();
    // layer 2: 64 -> 64
    float2 r = layer64(sW2, sb2, buf0, j);
    h0 = sp(r.x); h1 = sp(r.y);
    buf1[j] = h0; buf1[j + 32] = h1;
    __syncwarp();
    // layer 3: 64 -> 64
    r = layer64(sW3, sb3, buf1, j);
    h0 = sp(r.x); h1 = sp(r.y);
    // layer 4: 64 -> 5 (butterfly reduction across the warp)
#pragma unroll
    for (int o = 0; o < DIMN; ++o) {
        float2 w = sW4[o * 32 + j];
        float p = fmaf(w.x, h0, w.y * h1);
#pragma unroll
        for (int d = 16; d > 0; d >>= 1) p += __shfl_xor_sync(FULLMASK, p, d);
        k[o] = p + sb4[o];
    }
}

__global__ void __launch_bounds__(128, 3)
node_tsit5_kernel(const float* __restrict__ y0g, const float* __restrict__ teg,
                  const float* __restrict__ W1g, const float* __restrict__ b1g,
                  const float* __restrict__ W2g, const float* __restrict__ b2g,
                  const float* __restrict__ W3g, const float* __restrict__ b3g,
                  const float* __restrict__ W4g, const float* __restrict__ b4g,
                  float* __restrict__ outg) {
    __shared__ __align__(16) float sW2[64 * 68];
    __shared__ __align__(16) float sW3[64 * 68];
    __shared__ __align__(16) float sW1[64 * 5];
    __shared__ float sb1[64], sb2[64], sb3[64];
    __shared__ __align__(8) float2 sW4[5 * 32];
    __shared__ float sb4[8];
    __shared__ __align__(16) float ssh[4][2][64];  // per-warp double-buffered h scratch

    const int tid = threadIdx.x;
    // stage weights
    for (int e = tid; e < 64 * 64; e += 128) {
        int r = e >> 6, c = e & 63;
        sW2[r * 68 + c] = W2g[e];
        sW3[r * 68 + c] = W3g[e];
    }
    for (int e = tid; e < 64 * 5; e += 128) sW1[e] = W1g[e];
    if (tid < 64) { sb1[tid] = b1g[tid]; sb2[tid] = b2g[tid]; sb3[tid] = b3g[tid]; }
    if (tid < 5)  sb4[tid] = b4g[tid];
    for (int e = tid; e < 5 * 32; e += 128) {
        int o = e >> 5, jj = e & 31;
        sW4[e] = make_float2(W4g[o * 64 + jj], W4g[o * 64 + jj + 32]);
    }
    __syncthreads();

    const int warp = tid >> 5;
    const int j = tid & 31;
    const int b = blockIdx.x * 4 + warp;
    float* buf0 = &ssh[warp][0][0];
    float* buf1 = &ssh[warp][1][0];

    float y[DIMN];
#pragma unroll
    for (int d = 0; d < DIMN; ++d) y[d] = y0g[b * DIMN + d];
    const float te0 = teg[j];
    const float te1 = teg[j + 32];
    const float t0 = __shfl_sync(FULLMASK, te0, 0);
    const float t1 = __shfl_sync(FULLMASK, te1, 31);
    float* outb = outg + (size_t)b * NSAVE * DIMN;

    // initial save-point fill: y0 at/before t0, 0 elsewhere (matches reference init)
    {
        const bool m0 = (te0 <= t0 + EPSV);
        const bool m1 = (te1 <= t0 + EPSV);
#pragma unroll
        for (int d = 0; d < DIMN; ++d) outb[j * DIMN + d] = m0 ? y[d] : 0.0f;
#pragma unroll
        for (int d = 0; d < DIMN; ++d) outb[(j + 32) * DIMN + d] = m1 ? y[d] : 0.0f;
    }

    float t = t0, hstep = DT0V;
    float k1[DIMN], k2[DIMN], k3[DIMN], k4[DIMN], k5[DIMN], k6[DIMN], k7[DIMN];
    float ya[DIMN], ynew[DIMN];

    // FSAL seed
    feval(y, k1, sW1, sb1, sW2, sb2, sW3, sb3, sW4, sb4, buf0, buf1, j);

    for (int step = 0; step < 64; ++step) {
        if (t >= t1 - EPSV) break;  // remaining reference iterations are no-ops
        const float hc = fminf(hstep, t1 - t);

#pragma unroll
        for (int d = 0; d < DIMN; ++d) ya[d] = y[d] + hc * (A21f * k1[d]);
        feval(ya, k2, sW1, sb1, sW2, sb2, sW3, sb3, sW4, sb4, buf0, buf1, j);
#pragma unroll
        for (int d = 0; d < DIMN; ++d) ya[d] = y[d] + hc * (A31f * k1[d] + A32f * k2[d]);
        feval(ya, k3, sW1, sb1, sW2, sb2, sW3, sb3, sW4, sb4, buf0, buf1, j);
#pragma unroll
        for (int d = 0; d < DIMN; ++d)
            ya[d] = y[d] + hc * (A41f * k1[d] + A42f * k2[d] + A43f * k3[d]);
        feval(ya, k4, sW1, sb1, sW2, sb2, sW3, sb3, sW4, sb4, buf0, buf1, j);
#pragma unroll
        for (int d = 0; d < DIMN; ++d)
            ya[d] = y[d] + hc * (A51f * k1[d] + A52f * k2[d] + A53f * k3[d] + A54f * k4[d]);
        feval(ya, k5, sW1, sb1, sW2, sb2, sW3, sb3, sW4, sb4, buf0, buf1, j);
#pragma unroll
        for (int d = 0; d < DIMN; ++d)
            ya[d] = y[d] + hc * (A61f * k1[d] + A62f * k2[d] + A63f * k3[d] +
                                 A64f * k4[d] + A65f * k5[d]);
        feval(ya, k6, sW1, sb1, sW2, sb2, sW3, sb3, sW4, sb4, buf0, buf1, j);
#pragma unroll
        for (int d = 0; d < DIMN; ++d)
            ynew[d] = y[d] + hc * (B1f * k1[d] + B2f * k2[d] + B3f * k3[d] +
                                   B4f * k4[d] + B5f * k5[d] + B6f * k6[d]);
        feval(ynew, k7, sW1, sb1, sW2, sb2, sW3, sb3, sW4, sb4, buf0, buf1, j);

        float ss = 0.0f;
#pragma unroll
        for (int d = 0; d < DIMN; ++d) {
            float err = hc * (E1f * k1[d] + E2f * k2[d] + E3f * k3[d] + E4f * k4[d] +
                              E5f * k5[d] + E6f * k6[d] + E7f * k7[d]);
            float sc = 1e-6f + 1e-3f * fmaxf(fabsf(y[d]), fabsf(ynew[d]));
            float q = err / sc;
            ss += q * q;
        }
        const float enorm = sqrtf(ss * 0.2f);
        const bool accept = (enorm <= 1.0f);
        const float ec = fmaxf(enorm, 1e-10f);
        const float factor = fminf(fmaxf(0.9f * powf(ec, -0.2f), 0.2f), 10.0f);

        if (accept) {
            const float tn = t + hc;
            const float inv = 1.0f / fmaxf(hc, 1e-12f);
            // cubic Hermite interpolation at save points inside (t, tn]
            if (te0 > t && te0 <= tn + EPSV) {
                float s = (te0 - t) * inv, s2 = s * s, s3 = s2 * s;
                float h00 = 2.f * s3 - 3.f * s2 + 1.f;
                float h10 = s3 - 2.f * s2 + s;
                float h01 = -2.f * s3 + 3.f * s2;
                float h11 = s3 - s2;
#pragma unroll
                for (int d = 0; d < DIMN; ++d)
                    outb[j * DIMN + d] = h00 * y[d] + h10 * hc * k1[d] +
                                         h01 * ynew[d] + h11 * hc * k7[d];
            }
            if (te1 > t && te1 <= tn + EPSV) {
                float s = (te1 - t) * inv, s2 = s * s, s3 = s2 * s;
                float h00 = 2.f * s3 - 3.f * s2 + 1.f;
                float h10 = s3 - 2.f * s2 + s;
                float h01 = -2.f * s3 + 3.f * s2;
                float h11 = s3 - s2;
#pragma unroll
                for (int d = 0; d < DIMN; ++d)
                    outb[(j + 32) * DIMN + d] = h00 * y[d] + h10 * hc * k1[d] +
                                                h01 * ynew[d] + h11 * hc * k7[d];
            }
#pragma unroll
            for (int d = 0; d < DIMN; ++d) { y[d] = ynew[d]; k1[d] = k7[d]; }  // FSAL
            t = tn;
        }
        hstep = hc * factor;
    }
}

extern "C" void kernel_launch(void* const* d_in, const int* in_sizes, int n_in,
                              void* d_out, int out_size) {
    const float* y0 = (const float*)d_in[0];
    const float* te = (const float*)d_in[1];
    const float* W1 = (const float*)d_in[2];
    const float* b1 = (const float*)d_in[3];
    const float* W2 = (const float*)d_in[4];
    const float* b2 = (const float*)d_in[5];
    const float* W3 = (const float*)d_in[6];
    const float* b3 = (const float*)d_in[7];
    const float* W4 = (const float*)d_in[8];
    const float* b4 = (const float*)d_in[9];
    float* out = (float*)d_out;
    node_tsit5_kernel<<<BATCH / 4, 128>>>(y0, te, W1, b1, W2, b2, W3, b3, W4, b4, out);
}

// round 3
// speedup vs baseline: 1.2490x; 1.2490x over previous
#include <cuda_runtime.h>
#include <cstdint>

#define FULLMASK 0xFFFFFFFFu

#define DIMN   5
#define NSAVE  64
#define BATCH  4096
#define EPSV   1e-6f
#define DT0V   0.1f

#define A21f 0.161f
#define A31f -0.008480655492356989f
#define A32f 0.335480655492357f
#define A41f 2.8971530571054935f
#define A42f -6.359448489975075f
#define A43f 4.3622954328695815f
#define A51f 5.325864828439257f
#define A52f -11.748883564062828f
#define A53f 7.4955393428898365f
#define A54f -0.09249506636175525f
#define A61f 5.86145544294642f
#define A62f -12.92096931784711f
#define A63f 8.159367898576159f
#define A64f -0.071584973281401f
#define A65f -0.028269050394068383f
#define B1f 0.09646076681806523f
#define B2f 0.01f
#define B3f 0.4798896504144996f
#define B4f 1.379008574103742f
#define B5f -3.290069515436081f
#define B6f 2.324710524099774f
#define E1f -0.00178001105222577714f
#define E2f -0.0008164344596567469f
#define E3f 0.007880878010261995f
#define E4f -0.1447110071732629f
#define E5f 0.5823571654525552f
#define E6f -0.45808210592918697f
#define E7f 0.015151515151515152f

// fast softplus: max(x,0) + log1p(exp(-|x|)) via MUFU.EX2 / MUFU.LG2.
// abs err ~1e-7, far inside the 1e-3 gate.
static __device__ __forceinline__ float spf(float x) {
    return fmaxf(x, 0.0f) + __logf(1.0f + __expf(-fabsf(x)));
}

static __device__ __forceinline__ void fma2(unsigned long long &d,
                                            unsigned long long a,
                                            unsigned long long b) {
    asm("fma.rn.f32x2 %0, %1, %2, %0;" : "+l"(d) : "l"(a), "l"(b));
}
static __device__ __forceinline__ float2 asf2(unsigned long long u) {
    float2 f;
    asm("mov.b64 {%0, %1}, %2;" : "=f"(f.x), "=f"(f.y) : "l"(u));
    return f;
}

// 64->64 layer for TWO elements sharing one warp's weight loads.
// Lane j produces neurons j and j+32 for elements A and B.
// Wrow: smem row-major, stride 68 floats (conflict-free LDS.128 across lanes).
// hA/hB: 64-float activation buffers (warp-broadcast reads, ~free).
static __device__ __forceinline__ void layer64x2(const float* __restrict__ Wrow,
                                                 const float* __restrict__ bsm,
                                                 const float* __restrict__ hA,
                                                 const float* __restrict__ hB,
                                                 int j, float2 &oA, float2 &oB) {
    const ulonglong2* w0 = reinterpret_cast<const ulonglong2*>(Wrow + j * 68);
    const ulonglong2* w1 = reinterpret_cast<const ulonglong2*>(Wrow + (j + 32) * 68);
    const ulonglong2* ha = reinterpret_cast<const ulonglong2*>(hA);
    const ulonglong2* hb = reinterpret_cast<const ulonglong2*>(hB);
    unsigned long long aA0 = 0ull, aA1 = 0ull, aA2 = 0ull, aA3 = 0ull;
    unsigned long long aB0 = 0ull, aB1 = 0ull, aB2 = 0ull, aB3 = 0ull;
#pragma unroll
    for (int c = 0; c < 16; ++c) {
        ulonglong2 wa = w0[c];
        ulonglong2 wb = w1[c];
        ulonglong2 xa = ha[c];
        ulonglong2 xb = hb[c];
        fma2(aA0, wa.x, xa.x); fma2(aA1, wa.y, xa.y);
        fma2(aA2, wb.x, xa.x); fma2(aA3, wb.y, xa.y);
        fma2(aB0, wa.x, xb.x); fma2(aB1, wa.y, xb.y);
        fma2(aB2, wb.x, xb.x); fma2(aB3, wb.y, xb.y);
    }
    float2 fA0 = asf2(aA0), fA1 = asf2(aA1), fA2 = asf2(aA2), fA3 = asf2(aA3);
    float2 fB0 = asf2(aB0), fB1 = asf2(aB1), fB2 = asf2(aB2), fB3 = asf2(aB3);
    const float bj = bsm[j], bj2 = bsm[j + 32];
    oA.x = bj  + ((fA0.x + fA0.y) + (fA1.x + fA1.y));
    oA.y = bj2 + ((fA2.x + fA2.y) + (fA3.x + fA3.y));
    oB.x = bj  + ((fB0.x + fB0.y) + (fB1.x + fB1.y));
    oB.y = bj2 + ((fB2.x + fB2.y) + (fB3.x + fB3.y));
}

// MLP vector field for two elements; ya[e][5] replicated across lanes -> kk[e][5].
static __device__ __forceinline__ void feval2(const float ya[2][DIMN], float kk[2][DIMN],
                                              const float* __restrict__ sW1,
                                              const float* __restrict__ sb1,
                                              const float* __restrict__ sW2,
                                              const float* __restrict__ sb2,
                                              const float* __restrict__ sW3,
                                              const float* __restrict__ sb3,
                                              const float2* __restrict__ sW4,
                                              const float* __restrict__ sb4,
                                              float* bA0, float* bB0,
                                              float* bA1, float* bB1, int j) {
    // layer 1: 5 -> 64  (weight loads shared across elements)
    float a0A = sb1[j], a1A = sb1[j + 32];
    float a0B = a0A, a1B = a1A;
#pragma unroll
    for (int i = 0; i < DIMN; ++i) {
        const float w0 = sW1[j * DIMN + i];
        const float w1 = sW1[(j + 32) * DIMN + i];
        a0A = fmaf(w0, ya[0][i], a0A); a1A = fmaf(w1, ya[0][i], a1A);
        a0B = fmaf(w0, ya[1][i], a0B); a1B = fmaf(w1, ya[1][i], a1B);
    }
    bA0[j] = spf(a0A); bA0[j + 32] = spf(a1A);
    bB0[j] = spf(a0B); bB0[j + 32] = spf(a1B);
    __syncwarp();
    float2 rA, rB;
    layer64x2(sW2, sb2, bA0, bB0, j, rA, rB);
    bA1[j] = spf(rA.x); bA1[j + 32] = spf(rA.y);
    bB1[j] = spf(rB.x); bB1[j + 32] = spf(rB.y);
    __syncwarp();
    layer64x2(sW3, sb3, bA1, bB1, j, rA, rB);
    const float hA0 = spf(rA.x), hA1 = spf(rA.y);
    const float hB0 = spf(rB.x), hB1 = spf(rB.y);
    // layer 4: 64 -> 5, butterfly (shuffles also re-converge the warp)
#pragma unroll
    for (int o = 0; o < DIMN; ++o) {
        const float2 w = sW4[o * 32 + j];
        float pA = fmaf(w.x, hA0, w.y * hA1);
        float pB = fmaf(w.x, hB0, w.y * hB1);
#pragma unroll
        for (int d = 16; d > 0; d >>= 1) {
            pA += __shfl_xor_sync(FULLMASK, pA, d);
            pB += __shfl_xor_sync(FULLMASK, pB, d);
        }
        kk[0][o] = pA + sb4[o];
        kk[1][o] = pB + sb4[o];
    }
}

__global__ void __launch_bounds__(64)
node_tsit5_kernel(const float* __restrict__ y0g, const float* __restrict__ teg,
                  const float* __restrict__ W1g, const float* __restrict__ b1g,
                  const float* __restrict__ W2g, const float* __restrict__ b2g,
                  const float* __restrict__ W3g, const float* __restrict__ b3g,
                  const float* __restrict__ W4g, const float* __restrict__ b4g,
                  float* __restrict__ outg) {
    __shared__ __align__(16) float sW2[64 * 68];
    __shared__ __align__(16) float sW3[64 * 68];
    __shared__ __align__(16) float sW1[64 * DIMN];
    __shared__ float sb1[64], sb2[64], sb3[64];
    __shared__ __align__(8) float2 sW4[DIMN * 32];
    __shared__ float sb4[8];
    __shared__ __align__(16) float ssh[2][4][64];  // per-warp: hA0,hB0,hA1,hB1

    const int tid = threadIdx.x;
    // stage weights (float4; row stride 68 floats keeps 16B alignment: 272 % 16 == 0)
    for (int e = tid; e < 64 * 16; e += 64) {
        const int r = e >> 4, c = e & 15;
        reinterpret_cast<float4*>(sW2 + r * 68)[c] = reinterpret_cast<const float4*>(W2g)[e];
        reinterpret_cast<float4*>(sW3 + r * 68)[c] = reinterpret_cast<const float4*>(W3g)[e];
    }
    for (int e = tid; e < 64 * DIMN; e += 64) sW1[e] = W1g[e];
    sb1[tid] = b1g[tid]; sb2[tid] = b2g[tid]; sb3[tid] = b3g[tid];
    if (tid < 8) sb4[tid] = (tid < DIMN) ? b4g[tid] : 0.0f;
    for (int e = tid; e < DIMN * 32; e += 64) {
        const int o = e >> 5, jj = e & 31;
        sW4[e] = make_float2(W4g[o * 64 + jj], W4g[o * 64 + jj + 32]);
    }
    __syncthreads();

    const int warp = tid >> 5;
    const int j = tid & 31;
    const int bA = (blockIdx.x * 2 + warp) * 2;   // elements bA, bA+1
    float* bufA0 = &ssh[warp][0][0];
    float* bufB0 = &ssh[warp][1][0];
    float* bufA1 = &ssh[warp][2][0];
    float* bufB1 = &ssh[warp][3][0];

    float y[2][DIMN];
#pragma unroll
    for (int e = 0; e < 2; ++e)
#pragma unroll
        for (int d = 0; d < DIMN; ++d) y[e][d] = y0g[(bA + e) * DIMN + d];

    const float te0 = teg[j];
    const float te1 = teg[j + 32];
    const float t0 = __shfl_sync(FULLMASK, te0, 0);
    const float t1 = __shfl_sync(FULLMASK, te1, 31);
    float* outA = outg + (size_t)bA * NSAVE * DIMN;
    float* outB = outA + NSAVE * DIMN;

    // initial save fill (matches reference init)
    {
        const bool m0 = (te0 <= t0 + EPSV);
        const bool m1 = (te1 <= t0 + EPSV);
#pragma unroll
        for (int d = 0; d < DIMN; ++d) {
            outA[j * DIMN + d] = m0 ? y[0][d] : 0.0f;
            outA[(j + 32) * DIMN + d] = m1 ? y[0][d] : 0.0f;
            outB[j * DIMN + d] = m0 ? y[1][d] : 0.0f;
            outB[(j + 32) * DIMN + d] = m1 ? y[1][d] : 0.0f;
        }
    }

    float t[2] = {t0, t0};
    float hs[2] = {DT0V, DT0V};
    float k1[2][DIMN], k2[2][DIMN], k3[2][DIMN], k4[2][DIMN],
          k5[2][DIMN], k6[2][DIMN], k7[2][DIMN];
    float ya[2][DIMN], yn[2][DIMN];

    feval2(y, k1, sW1, sb1, sW2, sb2, sW3, sb3, sW4, sb4,
           bufA0, bufB0, bufA1, bufB1, j);  // FSAL seed

    for (int it = 0; it < 64; ++it) {
        const bool dn0 = (t[0] >= t1 - EPSV);
        const bool dn1 = (t[1] >= t1 - EPSV);
        if (dn0 && dn1) break;
        float hc[2];
        hc[0] = dn0 ? 0.0f : fminf(hs[0], t1 - t[0]);
        hc[1] = dn1 ? 0.0f : fminf(hs[1], t1 - t[1]);

#pragma unroll
        for (int e = 0; e < 2; ++e)
#pragma unroll
            for (int d = 0; d < DIMN; ++d)
                ya[e][d] = y[e][d] + hc[e] * (A21f * k1[e][d]);
        feval2(ya, k2, sW1, sb1, sW2, sb2, sW3, sb3, sW4, sb4, bufA0, bufB0, bufA1, bufB1, j);
#pragma unroll
        for (int e = 0; e < 2; ++e)
#pragma unroll
            for (int d = 0; d < DIMN; ++d)
                ya[e][d] = y[e][d] + hc[e] * (A31f * k1[e][d] + A32f * k2[e][d]);
        feval2(ya, k3, sW1, sb1, sW2, sb2, sW3, sb3, sW4, sb4, bufA0, bufB0, bufA1, bufB1, j);
#pragma unroll
        for (int e = 0; e < 2; ++e)
#pragma unroll
            for (int d = 0; d < DIMN; ++d)
                ya[e][d] = y[e][d] + hc[e] * (A41f * k1[e][d] + A42f * k2[e][d] + A43f * k3[e][d]);
        feval2(ya, k4, sW1, sb1, sW2, sb2, sW3, sb3, sW4, sb4, bufA0, bufB0, bufA1, bufB1, j);
#pragma unroll
        for (int e = 0; e < 2; ++e)
#pragma unroll
            for (int d = 0; d < DIMN; ++d)
                ya[e][d] = y[e][d] + hc[e] * (A51f * k1[e][d] + A52f * k2[e][d] +
                                              A53f * k3[e][d] + A54f * k4[e][d]);
        feval2(ya, k5, sW1, sb1, sW2, sb2, sW3, sb3, sW4, sb4, bufA0, bufB0, bufA1, bufB1, j);
#pragma unroll
        for (int e = 0; e < 2; ++e)
#pragma unroll
            for (int d = 0; d < DIMN; ++d)
                ya[e][d] = y[e][d] + hc[e] * (A61f * k1[e][d] + A62f * k2[e][d] + A63f * k3[e][d] +
                                              A64f * k4[e][d] + A65f * k5[e][d]);
        feval2(ya, k6, sW1, sb1, sW2, sb2, sW3, sb3, sW4, sb4, bufA0, bufB0, bufA1, bufB1, j);
#pragma unroll
        for (int e = 0; e < 2; ++e)
#pragma unroll
            for (int d = 0; d < DIMN; ++d)
                yn[e][d] = y[e][d] + hc[e] * (B1f * k1[e][d] + B2f * k2[e][d] + B3f * k3[e][d] +
                                              B4f * k4[e][d] + B5f * k5[e][d] + B6f * k6[e][d]);
        feval2(yn, k7, sW1, sb1, sW2, sb2, sW3, sb3, sW4, sb4, bufA0, bufB0, bufA1, bufB1, j);

#pragma unroll
        for (int e = 0; e < 2; ++e) {
            const bool dn = (e == 0) ? dn0 : dn1;
            float ss = 0.0f;
#pragma unroll
            for (int d = 0; d < DIMN; ++d) {
                const float err = hc[e] * (E1f * k1[e][d] + E2f * k2[e][d] + E3f * k3[e][d] +
                                           E4f * k4[e][d] + E5f * k5[e][d] + E6f * k6[e][d] +
                                           E7f * k7[e][d]);
                const float sc = 1e-6f + 1e-3f * fmaxf(fabsf(y[e][d]), fabsf(yn[e][d]));
                const float q = err / sc;
                ss = fmaf(q, q, ss);
            }
            const float enorm = sqrtf(ss * 0.2f);
            const bool accept = (enorm <= 1.0f);
            const float ec = fmaxf(enorm, 1e-10f);
            const float factor = fminf(fmaxf(0.9f * powf(ec, -0.2f), 0.2f), 10.0f);

            if (!dn && accept) {
                const float tn = t[e] + hc[e];
                const float inv = 1.0f / fmaxf(hc[e], 1e-12f);
                float* outb = (e == 0) ? outA : outB;
                if (te0 > t[e] && te0 <= tn + EPSV) {
                    const float s = (te0 - t[e]) * inv, s2 = s * s, s3 = s2 * s;
                    const float h00 = 2.f * s3 - 3.f * s2 + 1.f;
                    const float h10 = s3 - 2.f * s2 + s;
                    const float h01 = -2.f * s3 + 3.f * s2;
                    const float h11 = s3 - s2;
#pragma unroll
                    for (int d = 0; d < DIMN; ++d)
                        outb[j * DIMN + d] = h00 * y[e][d] + h10 * hc[e] * k1[e][d] +
                                             h01 * yn[e][d] + h11 * hc[e] * k7[e][d];
                }
                if (te1 > t[e] && te1 <= tn + EPSV) {
                    const float s = (te1 - t[e]) * inv, s2 = s * s, s3 = s2 * s;
                    const float h00 = 2.f * s3 - 3.f * s2 + 1.f;
                    const float h10 = s3 - 2.f * s2 + s;
                    const float h01 = -2.f * s3 + 3.f * s2;
                    const float h11 = s3 - s2;
#pragma unroll
                    for (int d = 0; d < DIMN; ++d)
                        outb[(j + 32) * DIMN + d] = h00 * y[e][d] + h10 * hc[e] * k1[e][d] +
                                                    h01 * yn[e][d] + h11 * hc[e] * k7[e][d];
                }
#pragma unroll
                for (int d = 0; d < DIMN; ++d) { y[e][d] = yn[e][d]; k1[e][d] = k7[e][d]; }
                t[e] = tn;
            }
            if (!dn) hs[e] = hc[e] * factor;
        }
    }
}

extern "C" void kernel_launch(void* const* d_in, const int* in_sizes, int n_in,
                              void* d_out, int out_size) {
    const float* y0 = (const float*)d_in[0];
    const float* te = (const float*)d_in[1];
    const float* W1 = (const float*)d_in[2];
    const float* b1 = (const float*)d_in[3];
    const float* W2 = (const float*)d_in[4];
    const float* b2 = (const float*)d_in[5];
    const float* W3 = (const float*)d_in[6];
    const float* b3 = (const float*)d_in[7];
    const float* W4 = (const float*)d_in[8];
    const float* b4 = (const float*)d_in[9];
    float* out = (float*)d_out;
    // 2 elements per warp, 2 warps per CTA -> 4 elements per CTA
    node_tsit5_kernel<<<BATCH / 4, 64>>>(y0, te, W1, b1, W2, b2, W3, b3, W4, b4, out);
}

// round 4
// speedup vs baseline: 1.2659x; 1.0135x over previous
#include <cuda_runtime.h>
#include <cstdint>

#define FULLMASK 0xFFFFFFFFu

#define DIMN   5
#define NSAVE  64
#define BATCH  4096
#define EPSV   1e-6f
#define DT0V   0.1f
#define NELEM  4     // elements per warp

#define A21f 0.161f
#define A31f -0.008480655492356989f
#define A32f 0.335480655492357f
#define A41f 2.8971530571054935f
#define A42f -6.359448489975075f
#define A43f 4.3622954328695815f
#define A51f 5.325864828439257f
#define A52f -11.748883564062828f
#define A53f 7.4955393428898365f
#define A54f -0.09249506636175525f
#define A61f 5.86145544294642f
#define A62f -12.92096931784711f
#define A63f 8.159367898576159f
#define A64f -0.071584973281401f
#define A65f -0.028269050394068383f
#define B1f 0.09646076681806523f
#define B2f 0.01f
#define B3f 0.4798896504144996f
#define B4f 1.379008574103742f
#define B5f -3.290069515436081f
#define B6f 2.324710524099774f
#define E1f -0.00178001105222577714f
#define E2f -0.0008164344596567469f
#define E3f 0.007880878010261995f
#define E4f -0.1447110071732629f
#define E5f 0.5823571654525552f
#define E6f -0.45808210592918697f
#define E7f 0.015151515151515152f

// fast softplus (MUFU.EX2/LG2), abs err ~1e-7 — far inside the 1e-3 gate
static __device__ __forceinline__ float spf(float x) {
    return fmaxf(x, 0.0f) + __logf(1.0f + __expf(-fabsf(x)));
}

static __device__ __forceinline__ void fma2(unsigned long long &d,
                                            unsigned long long a,
                                            unsigned long long b) {
    asm("fma.rn.f32x2 %0, %1, %2, %0;" : "+l"(d) : "l"(a), "l"(b));
}
static __device__ __forceinline__ float2 asf2(unsigned long long u) {
    float2 f;
    asm("mov.b64 {%0, %1}, %2;" : "=f"(f.x), "=f"(f.y) : "l"(u));
    return f;
}

// 64->64 layer for FOUR elements sharing one warp's weight loads.
// Lane j -> output neurons j, j+32. Wrow stride 68 floats (conflict-free LDS.128).
static __device__ __forceinline__ void layer64x4(const float* __restrict__ Wrow,
                                                 const float* __restrict__ bsm,
                                                 const float* __restrict__ hbuf,  // [4][64]
                                                 int j, float2 out[NELEM]) {
    const ulonglong2* w0 = reinterpret_cast<const ulonglong2*>(Wrow + j * 68);
    const ulonglong2* w1 = reinterpret_cast<const ulonglong2*>(Wrow + (j + 32) * 68);
    unsigned long long A[NELEM][4];
#pragma unroll
    for (int e = 0; e < NELEM; ++e)
#pragma unroll
        for (int q = 0; q < 4; ++q) A[e][q] = 0ull;
#pragma unroll
    for (int c = 0; c < 16; ++c) {
        const ulonglong2 wa = w0[c];
        const ulonglong2 wb = w1[c];
#pragma unroll
        for (int e = 0; e < NELEM; ++e) {
            const ulonglong2 x =
                reinterpret_cast<const ulonglong2*>(hbuf + e * 64)[c];
            fma2(A[e][0], wa.x, x.x); fma2(A[e][1], wa.y, x.y);
            fma2(A[e][2], wb.x, x.x); fma2(A[e][3], wb.y, x.y);
        }
    }
    const float bj = bsm[j], bj2 = bsm[j + 32];
#pragma unroll
    for (int e = 0; e < NELEM; ++e) {
        const float2 f0 = asf2(A[e][0]), f1 = asf2(A[e][1]);
        const float2 f2 = asf2(A[e][2]), f3 = asf2(A[e][3]);
        out[e].x = bj  + ((f0.x + f0.y) + (f1.x + f1.y));
        out[e].y = bj2 + ((f2.x + f2.y) + (f3.x + f3.y));
    }
}

// MLP for 4 elements. Stage inputs in yax[e*8+d] (smem). Result kk[e] lane-sliced:
// lane j<5 ends holding dim j of k for each element.
static __device__ __forceinline__ void feval4(const float* __restrict__ yax,
                                              float kk[NELEM],
                                              const float* __restrict__ sW1,
                                              const float* __restrict__ sb1,
                                              const float* __restrict__ sW2,
                                              const float* __restrict__ sb2,
                                              const float* __restrict__ sW3,
                                              const float* __restrict__ sb3,
                                              const float2* __restrict__ sW4,
                                              const float* __restrict__ sb4,
                                              float* __restrict__ buf0,
                                              float* __restrict__ buf1, int j) {
    __syncwarp();
    // layer 1: 5 -> 64
    {
        const float b0 = sb1[j], b1 = sb1[j + 32];
        float w0r[DIMN], w1r[DIMN];
#pragma unroll
        for (int i = 0; i < DIMN; ++i) {
            w0r[i] = sW1[j * DIMN + i];
            w1r[i] = sW1[(j + 32) * DIMN + i];
        }
#pragma unroll
        for (int e = 0; e < NELEM; ++e) {
            const float4 x4 = *reinterpret_cast<const float4*>(yax + e * 8);
            const float x5 = yax[e * 8 + 4];
            float a0 = b0, a1 = b1;
            a0 = fmaf(w0r[0], x4.x, a0); a1 = fmaf(w1r[0], x4.x, a1);
            a0 = fmaf(w0r[1], x4.y, a0); a1 = fmaf(w1r[1], x4.y, a1);
            a0 = fmaf(w0r[2], x4.z, a0); a1 = fmaf(w1r[2], x4.z, a1);
            a0 = fmaf(w0r[3], x4.w, a0); a1 = fmaf(w1r[3], x4.w, a1);
            a0 = fmaf(w0r[4], x5, a0);   a1 = fmaf(w1r[4], x5, a1);
            buf0[e * 64 + j] = spf(a0);
            buf0[e * 64 + 32 + j] = spf(a1);
        }
    }
    __syncwarp();
    float2 r[NELEM];
    layer64x4(sW2, sb2, buf0, j, r);
#pragma unroll
    for (int e = 0; e < NELEM; ++e) {
        buf1[e * 64 + j] = spf(r[e].x);
        buf1[e * 64 + 32 + j] = spf(r[e].y);
    }
    __syncwarp();
    layer64x4(sW3, sb3, buf1, j, r);
    float h0[NELEM], h1[NELEM];
#pragma unroll
    for (int e = 0; e < NELEM; ++e) { h0[e] = spf(r[e].x); h1[e] = spf(r[e].y); }
    // layer 4: 64 -> 5, butterfly; lane o keeps output o
#pragma unroll
    for (int o = 0; o < DIMN; ++o) {
        const float2 w = sW4[o * 32 + j];
        float p[NELEM];
#pragma unroll
        for (int e = 0; e < NELEM; ++e) p[e] = fmaf(w.x, h0[e], w.y * h1[e]);
#pragma unroll
        for (int s = 16; s > 0; s >>= 1)
#pragma unroll
            for (int e = 0; e < NELEM; ++e)
                p[e] += __shfl_xor_sync(FULLMASK, p[e], s);
        const float bo = sb4[o];
        if (j == o) {
#pragma unroll
            for (int e = 0; e < NELEM; ++e) kk[e] = p[e] + bo;
        }
    }
}

__global__ void __launch_bounds__(64)
node_tsit5_kernel(const float* __restrict__ y0g, const float* __restrict__ teg,
                  const float* __restrict__ W1g, const float* __restrict__ b1g,
                  const float* __restrict__ W2g, const float* __restrict__ b2g,
                  const float* __restrict__ W3g, const float* __restrict__ b3g,
                  const float* __restrict__ W4g, const float* __restrict__ b4g,
                  float* __restrict__ outg) {
    __shared__ __align__(16) float sW2[64 * 68];
    __shared__ __align__(16) float sW3[64 * 68];
    __shared__ __align__(16) float sW1[64 * DIMN];
    __shared__ float sb1[64], sb2[64], sb3[64];
    __shared__ __align__(8) float2 sW4[DIMN * 32];
    __shared__ float sb4[8];
    __shared__ __align__(16) float ssh[2][2 * NELEM][64];   // per-warp h buffers
    __shared__ __align__(16) float syax[2][NELEM][8];        // per-warp stage inputs
    __shared__ __align__(16) float ssc[2][NELEM][32];        // per-warp interp scratch

    const int tid = threadIdx.x;
    for (int e = tid; e < 64 * 16; e += 64) {
        const int r = e >> 4, c = e & 15;
        reinterpret_cast<float4*>(sW2 + r * 68)[c] = reinterpret_cast<const float4*>(W2g)[e];
        reinterpret_cast<float4*>(sW3 + r * 68)[c] = reinterpret_cast<const float4*>(W3g)[e];
    }
    for (int e = tid; e < 64 * DIMN; e += 64) sW1[e] = W1g[e];
    sb1[tid] = b1g[tid]; sb2[tid] = b2g[tid]; sb3[tid] = b3g[tid];
    if (tid < 8) sb4[tid] = (tid < DIMN) ? b4g[tid] : 0.0f;
    for (int e = tid; e < DIMN * 32; e += 64) {
        const int o = e >> 5, jj = e & 31;
        sW4[e] = make_float2(W4g[o * 64 + jj], W4g[o * 64 + jj + 32]);
    }
    __syncthreads();

    const int warp = tid >> 5;
    const int j = tid & 31;
    const int bA = (blockIdx.x * 2 + warp) * NELEM;
    float* buf0 = &ssh[warp][0][0];
    float* buf1 = &ssh[warp][NELEM][0];
    float* yax  = &syax[warp][0][0];
    float* scc  = &ssc[warp][0][0];

    const float te0 = teg[j];
    const float te1 = teg[j + 32];
    const float t0 = __shfl_sync(FULLMASK, te0, 0);
    const float t1 = __shfl_sync(FULLMASK, te1, 31);

    // lane-sliced y: lane j<5 holds dim j
    float y[NELEM];
#pragma unroll
    for (int e = 0; e < NELEM; ++e)
        y[e] = (j < DIMN) ? y0g[(bA + e) * DIMN + j] : 0.0f;

    // initial save fill (matches reference init); read y0 directly (L1-cached)
#pragma unroll
    for (int e = 0; e < NELEM; ++e) {
        const float* y0e = y0g + (bA + e) * DIMN;
        float* outb = outg + (size_t)(bA + e) * NSAVE * DIMN;
        const bool m0 = (te0 <= t0 + EPSV);
        const bool m1 = (te1 <= t0 + EPSV);
#pragma unroll
        for (int d = 0; d < DIMN; ++d) {
            const float v = y0e[d];
            outb[j * DIMN + d] = m0 ? v : 0.0f;
            outb[(j + 32) * DIMN + d] = m1 ? v : 0.0f;
        }
    }

    float t[NELEM], hs[NELEM];
    float k1[NELEM], k2[NELEM], k3[NELEM], k4[NELEM], k5[NELEM], k6[NELEM], k7[NELEM];
#pragma unroll
    for (int e = 0; e < NELEM; ++e) {
        t[e] = t0; hs[e] = DT0V;
        k1[e] = k2[e] = k3[e] = k4[e] = k5[e] = k6[e] = k7[e] = 0.0f;
    }

    // FSAL seed
    if (j < DIMN) {
#pragma unroll
        for (int e = 0; e < NELEM; ++e) yax[e * 8 + j] = y[e];
    }
    feval4(yax, k1, sW1, sb1, sW2, sb2, sW3, sb3, sW4, sb4, buf0, buf1, j);

    float yn[NELEM], hc[NELEM];
    bool dn[NELEM];

    for (int it = 0; it < 64; ++it) {
        bool alldone = true;
#pragma unroll
        for (int e = 0; e < NELEM; ++e) {
            dn[e] = (t[e] >= t1 - EPSV);
            alldone = alldone && dn[e];
        }
        if (alldone) break;
#pragma unroll
        for (int e = 0; e < NELEM; ++e)
            hc[e] = dn[e] ? 0.0f : fminf(hs[e], t1 - t[e]);

#pragma unroll
        for (int e = 0; e < NELEM; ++e) {
            const float v = y[e] + hc[e] * (A21f * k1[e]);
            if (j < DIMN) yax[e * 8 + j] = v;
        }
        feval4(yax, k2, sW1, sb1, sW2, sb2, sW3, sb3, sW4, sb4, buf0, buf1, j);
#pragma unroll
        for (int e = 0; e < NELEM; ++e) {
            const float v = y[e] + hc[e] * (A31f * k1[e] + A32f * k2[e]);
            if (j < DIMN) yax[e * 8 + j] = v;
        }
        feval4(yax, k3, sW1, sb1, sW2, sb2, sW3, sb3, sW4, sb4, buf0, buf1, j);
#pragma unroll
        for (int e = 0; e < NELEM; ++e) {
            const float v = y[e] + hc[e] * (A41f * k1[e] + A42f * k2[e] + A43f * k3[e]);
            if (j < DIMN) yax[e * 8 + j] = v;
        }
        feval4(yax, k4, sW1, sb1, sW2, sb2, sW3, sb3, sW4, sb4, buf0, buf1, j);
#pragma unroll
        for (int e = 0; e < NELEM; ++e) {
            const float v = y[e] + hc[e] * (A51f * k1[e] + A52f * k2[e] +
                                            A53f * k3[e] + A54f * k4[e]);
            if (j < DIMN) yax[e * 8 + j] = v;
        }
        feval4(yax, k5, sW1, sb1, sW2, sb2, sW3, sb3, sW4, sb4, buf0, buf1, j);
#pragma unroll
        for (int e = 0; e < NELEM; ++e) {
            const float v = y[e] + hc[e] * (A61f * k1[e] + A62f * k2[e] + A63f * k3[e] +
                                            A64f * k4[e] + A65f * k5[e]);
            if (j < DIMN) yax[e * 8 + j] = v;
        }
        feval4(yax, k6, sW1, sb1, sW2, sb2, sW3, sb3, sW4, sb4, buf0, buf1, j);
#pragma unroll
        for (int e = 0; e < NELEM; ++e) {
            yn[e] = y[e] + hc[e] * (B1f * k1[e] + B2f * k2[e] + B3f * k3[e] +
                                    B4f * k4[e] + B5f * k5[e] + B6f * k6[e]);
            if (j < DIMN) yax[e * 8 + j] = yn[e];
        }
        feval4(yax, k7, sW1, sb1, sW2, sb2, sW3, sb3, sW4, sb4, buf0, buf1, j);

#pragma unroll
        for (int e = 0; e < NELEM; ++e) {
            // error norm: lane j<5 contributes dim j; gather -> all lanes get ss
            const float err = hc[e] * (E1f * k1[e] + E2f * k2[e] + E3f * k3[e] +
                                       E4f * k4[e] + E5f * k5[e] + E6f * k6[e] +
                                       E7f * k7[e]);
            const float sc = 1e-6f + 1e-3f * fmaxf(fabsf(y[e]), fabsf(yn[e]));
            const float q = err / sc;
            const float q2 = q * q;
            float ss = __shfl_sync(FULLMASK, q2, 0);
            ss += __shfl_sync(FULLMASK, q2, 1);
            ss += __shfl_sync(FULLMASK, q2, 2);
            ss += __shfl_sync(FULLMASK, q2, 3);
            ss += __shfl_sync(FULLMASK, q2, 4);
            const float enorm = sqrtf(ss * 0.2f);
            const bool accept = (enorm <= 1.0f);
            const float ec = fmaxf(enorm, 1e-10f);
            const float factor = fminf(fmaxf(0.9f * powf(ec, -0.2f), 0.2f), 10.0f);

            if (!dn[e] && accept) {   // warp-uniform
                const float tn = t[e] + hc[e];
                float* s = scc + e * 32;  // [0:8)=y [8:16)=yn [16:24)=hc*k1 [24:32)=hc*k7
                if (j < DIMN) {
                    s[j] = y[e];
                    s[8 + j] = yn[e];
                    s[16 + j] = hc[e] * k1[e];
                    s[24 + j] = hc[e] * k7[e];
                }
                __syncwarp();
                const float inv = 1.0f / fmaxf(hc[e], 1e-12f);
                float* outb = outg + (size_t)(bA + e) * NSAVE * DIMN;
                if (te0 > t[e] && te0 <= tn + EPSV) {
                    const float sv = (te0 - t[e]) * inv, s2 = sv * sv, s3 = s2 * sv;
                    const float h00 = 2.f * s3 - 3.f * s2 + 1.f;
                    const float h10 = s3 - 2.f * s2 + sv;
                    const float h01 = -2.f * s3 + 3.f * s2;
                    const float h11 = s3 - s2;
#pragma unroll
                    for (int d = 0; d < DIMN; ++d)
                        outb[j * DIMN + d] = h00 * s[d] + h10 * s[16 + d] +
                                             h01 * s[8 + d] + h11 * s[24 + d];
                }
                if (te1 > t[e] && te1 <= tn + EPSV) {
                    const float sv = (te1 - t[e]) * inv, s2 = sv * sv, s3 = s2 * sv;
                    const float h00 = 2.f * s3 - 3.f * s2 + 1.f;
                    const float h10 = s3 - 2.f * s2 + sv;
                    const float h01 = -2.f * s3 + 3.f * s2;
                    const float h11 = s3 - s2;
#pragma unroll
                    for (int d = 0; d < DIMN; ++d)
                        outb[(j + 32) * DIMN + d] = h00 * s[d] + h10 * s[16 + d] +
                                                    h01 * s[8 + d] + h11 * s[24 + d];
                }
                y[e] = yn[e];
                k1[e] = k7[e];   // FSAL
                t[e] = tn;
            }
            if (!dn[e]) hs[e] = hc[e] * factor;
        }
    }
}

extern "C" void kernel_launch(void* const* d_in, const int* in_sizes, int n_in,
                              void* d_out, int out_size) {
    const float* y0 = (const float*)d_in[0];
    const float* te = (const float*)d_in[1];
    const float* W1 = (const float*)d_in[2];
    const float* b1 = (const float*)d_in[3];
    const float* W2 = (const float*)d_in[4];
    const float* b2 = (const float*)d_in[5];
    const float* W3 = (const float*)d_in[6];
    const float* b3 = (const float*)d_in[7];
    const float* W4 = (const float*)d_in[8];
    const float* b4 = (const float*)d_in[9];
    float* out = (float*)d_out;
    // 4 elements per warp, 2 warps per CTA -> 8 elements per CTA
    node_tsit5_kernel<<<BATCH / (2 * NELEM), 64>>>(y0, te, W1, b1, W2, b2, W3, b3, W4, b4, out);
}